// round 13
// baseline (speedup 1.0000x reference)
#include <cuda_runtime.h>
#include <cuda_fp16.h>
#include <math_constants.h>
#include <cstdint>

#define BB 4
#define SS 2048
#define DD 1024
#define MM (BB*SS)          // 8192 rows
#define DH 512              // stored half-spectrum bins (Nyquist packed into bin0.y)
#define NCHUNK 64
#define CHUNKLEN (SS/NCHUNK) // 32

// GEMM tiling
#define MT 128
#define NT 128
#define KC 64
#define NKCH (DD/KC)        // 16

// convert-kernel grid split
#define XBLK ((MM * DD) / 1024)   // 8192
#define WBLK ((DD * DD) / 1024)   // 1024

// ---------------- scratch (static device memory; no allocations) -------------
__device__ __half  g_qkv[3][MM][DD];                // Q,K,V fp16  (48 MB)
__device__ __half2 g_fq[(size_t)MM * DH];           // FQ fp16; overwritten as FOUT/1024
__device__ __half2 g_fk[(size_t)MM * DH];           // FK fp16 complex (16.8 MB)
__device__ __half2 g_fv[(size_t)MM * DH];           // FV fp16 complex (16.8 MB)
__device__ float2  g_chunk[BB][NCHUNK][DH];         // per-chunk partial sums (1 MB)
__device__ __half  g_x16[(size_t)MM * DD];          // 16 MB
__device__ __half  g_w[3][DD * DD];                 // 6 MB

// ---------------- PTX helpers -------------------------------------------------
__device__ __forceinline__ uint32_t smem_u32(const void* p) {
    uint32_t a;
    asm("{ .reg .u64 t; cvta.to.shared.u64 t, %1; cvt.u32.u64 %0, t; }" : "=r"(a) : "l"(p));
    return a;
}
__device__ __forceinline__ void cp16(uint32_t dst, const void* src) {
    asm volatile("cp.async.cg.shared.global [%0], [%1], 16;" :: "r"(dst), "l"(src) : "memory");
}
__device__ __forceinline__ void cp_commit() { asm volatile("cp.async.commit_group;" ::: "memory"); }
__device__ __forceinline__ void cp_wait2()  { asm volatile("cp.async.wait_group 2;" ::: "memory"); }

__device__ __forceinline__ void ldsm4(uint32_t* r, uint32_t addr) {
    asm volatile("ldmatrix.sync.aligned.m8n8.x4.shared.b16 {%0,%1,%2,%3}, [%4];"
        : "=r"(r[0]), "=r"(r[1]), "=r"(r[2]), "=r"(r[3]) : "r"(addr));
}
__device__ __forceinline__ void hmma(float* c, const uint32_t* a, const uint32_t* b) {
    asm volatile("mma.sync.aligned.m16n8k16.row.col.f32.f16.f16.f32 "
        "{%0,%1,%2,%3}, {%4,%5,%6,%7}, {%8,%9}, {%0,%1,%2,%3};"
        : "+f"(c[0]), "+f"(c[1]), "+f"(c[2]), "+f"(c[3])
        : "r"(a[0]), "r"(a[1]), "r"(a[2]), "r"(a[3]), "r"(b[0]), "r"(b[1]));
}

// ---------------- fused fp16 convert kernel -----------------------------------
__global__ __launch_bounds__(256) void conv_all(const float* __restrict__ X,
                                                const float* __restrict__ Wq,
                                                const float* __restrict__ Wk,
                                                const float* __restrict__ Wv) {
    const int b = blockIdx.x;
    const float* __restrict__ src;
    __half* __restrict__ dst;
    int blk;
    if (b < XBLK) {
        src = X; dst = g_x16; blk = b;
    } else {
        int wb = b - XBLK;
        int which = wb / WBLK;
        src = (which == 0) ? Wq : (which == 1) ? Wk : Wv;
        dst = g_w[which];
        blk = wb - which * WBLK;
    }
    size_t i = ((size_t)blk * 256 + threadIdx.x) * 4;
    float4 v = *(const float4*)(src + i);
    __half h[4];
    h[0] = __float2half_rn(v.x);
    h[1] = __float2half_rn(v.y);
    h[2] = __float2half_rn(v.z);
    h[3] = __float2half_rn(v.w);
    *(uint2*)&dst[i] = *(uint2*)h;
}

// ---------------- HMMA GEMM: Y = X * W^T  (fp16, fp32 accum, fp16 out) --------
#define GSM_BUF   32768
#define OFF_A     0
#define OFF_B     16384
#define GEMM_SMEM_BYTES (100 * 1024)

__device__ __forceinline__ uint32_t sw128(uint32_t bo) {
    return bo ^ ((bo >> 3) & 0x70);
}

__device__ __forceinline__ void load_chunk(uint32_t sb, int buf, int ch, int m0, int n0, int tid,
                                           const __half* __restrict__ Ax,
                                           const __half* __restrict__ Bw) {
    const int c0 = ch * KC;
    const uint32_t base = sb + buf * GSM_BUF;
#pragma unroll
    for (int i = 0; i < 4; i++) {
        int seg = tid + i * 256;
        int row = seg >> 3;
        int sc  = seg & 7;
        uint32_t sw = sw128((uint32_t)(row * 128 + sc * 16));
        size_t ga = (size_t)(m0 + row) * DD + c0 + sc * 8;
        size_t gb = (size_t)(n0 + row) * DD + c0 + sc * 8;
        cp16(base + OFF_A + sw, Ax + ga);
        cp16(base + OFF_B + sw, Bw + gb);
    }
}

__global__ __launch_bounds__(256) void gemm_hmma() {
    extern __shared__ __align__(16) char smem_raw[];
    uint32_t raw = smem_u32(smem_raw);
    uint32_t sb = (raw + 1023) & ~1023u;

    const int tid = threadIdx.x;
    const int wid = tid >> 5;
    const int l   = tid & 31;
    const int which = blockIdx.z;
    const int m0 = blockIdx.y * MT;
    const int n0 = blockIdx.x * NT;
    const int warp_m = (wid & 3) * 32;
    const int warp_n = (wid >> 2) * 64;

    const __half* __restrict__ Ax = g_x16;
    const __half* __restrict__ Bw = g_w[which];
    __half* __restrict__ Y = &g_qkv[which][0][0];

    float acc[2][8][4];
#pragma unroll
    for (int i = 0; i < 2; i++)
#pragma unroll
        for (int j = 0; j < 8; j++)
#pragma unroll
            for (int k = 0; k < 4; k++) acc[i][j][k] = 0.f;

    const int a_row = (l & 15);
    const int a_k16 = (l >> 4);
    const int b_row = (l & 7) + ((l >> 4) & 1) * 8;
    const int b_k16 = (l >> 3) & 1;

    load_chunk(sb, 0, 0, m0, n0, tid, Ax, Bw);
    cp_commit();
    load_chunk(sb, 1, 1, m0, n0, tid, Ax, Bw);
    cp_commit();

    for (int c = 0; c < NKCH; c++) {
        if (c + 2 < NKCH)
            load_chunk(sb, (c + 2) % 3, c + 2, m0, n0, tid, Ax, Bw);
        cp_commit();
        cp_wait2();
        __syncthreads();

        const uint32_t base = sb + (c % 3) * GSM_BUF;
#pragma unroll
        for (int ks = 0; ks < 4; ks++) {
            uint32_t ax[2][4], bw[8][2];
#pragma unroll
            for (int mt = 0; mt < 2; mt++) {
                uint32_t bo = (uint32_t)((warp_m + mt * 16 + a_row) * 128 + (ks * 2 + a_k16) * 16);
                uint32_t sw = sw128(bo);
                ldsm4(ax[mt], base + OFF_A + sw);
            }
#pragma unroll
            for (int p = 0; p < 4; p++) {
                uint32_t bo = (uint32_t)((warp_n + p * 16 + b_row) * 128 + (ks * 2 + b_k16) * 16);
                uint32_t sw = sw128(bo);
                uint32_t r[4];
                ldsm4(r, base + OFF_B + sw);
                bw[2 * p][0] = r[0]; bw[2 * p][1] = r[1];
                bw[2 * p + 1][0] = r[2]; bw[2 * p + 1][1] = r[3];
            }
#pragma unroll
            for (int mt = 0; mt < 2; mt++)
#pragma unroll
                for (int nt = 0; nt < 8; nt++)
                    hmma(acc[mt][nt], ax[mt], bw[nt]);
        }
        __syncthreads();
    }

    const int g = l >> 2;
    const int t = l & 3;
#pragma unroll
    for (int mt = 0; mt < 2; mt++)
#pragma unroll
        for (int nt = 0; nt < 8; nt++) {
            int m = m0 + warp_m + mt * 16 + g;
            int n = n0 + warp_n + nt * 8 + t * 2;
            __half2 h01 = __floats2half2_rn(acc[mt][nt][0], acc[mt][nt][1]);
            __half2 h23 = __floats2half2_rn(acc[mt][nt][2], acc[mt][nt][3]);
            *(__half2*)&Y[(size_t)m * DD + n]       = h01;
            *(__half2*)&Y[(size_t)(m + 8) * DD + n] = h23;
        }
}

// ---------------- 1024-point complex FFT (radix-4 Stockham, bank-aware) -------
__device__ __forceinline__ float2 cadd(float2 a, float2 b) { return make_float2(a.x + b.x, a.y + b.y); }
__device__ __forceinline__ float2 csub(float2 a, float2 b) { return make_float2(a.x - b.x, a.y - b.y); }
__device__ __forceinline__ float2 cmul(float2 a, float2 b) {
    return make_float2(a.x * b.x - a.y * b.y, a.x * b.y + a.y * b.x);
}

__device__ __forceinline__ int mapA(int i) { return i + ((i >> 4) << 2); }
__device__ __forceinline__ int mapB(int i) { return i ^ ((i >> 4) & 3); }

// twiddle table: tw1[p] = e^{-2pi i p/1024}, tw2[p] = tw1[p]^2, p = j*M in 0..255
__device__ __forceinline__ void build_tw(float2* tw1, float2* tw2, int t)
{
#pragma unroll
    for (int i = t; i < 256; i += 128) {
        float ang = -(2.0f * (float)CUDART_PI_F / 1024.0f) * (float)i;
        float sn, cs;
        __sincosf(ang, &sn, &cs);
        float2 w1 = make_float2(cs, sn);
        tw1[i] = w1;
        tw2[i] = cmul(w1, w1);
    }
}

template<int M, int SEL>
__device__ __forceinline__ void r4stage(const float2* __restrict__ x, float2* __restrict__ y,
                                        const float2* __restrict__ tw1,
                                        const float2* __restrict__ tw2, int t)
{
#pragma unroll
    for (int q = 0; q < 2; q++) {
        int bf = t + q * 128;
        int j = bf / M;
        int k = bf - j * M;
        float2 c0 = x[SEL ? mapB(bf)       : mapA(bf)];
        float2 c1 = x[SEL ? mapB(bf + 256) : mapA(bf + 256)];
        float2 c2 = x[SEL ? mapB(bf + 512) : mapA(bf + 512)];
        float2 c3 = x[SEL ? mapB(bf + 768) : mapA(bf + 768)];
        float2 t0 = cadd(c0, c2);
        float2 t1 = csub(c0, c2);
        float2 t2 = cadd(c1, c3);
        float2 d  = csub(c1, c3);
        float2 t3 = make_float2(d.y, -d.x);   // -i * d
        int p = bf & ~(M - 1);                // j*M
        float2 w1 = tw1[p];
        float2 w2 = tw2[p];
        float2 w3 = cmul(w1, w2);
        int o = k + 4 * j * M;
        float2 r0 = cadd(t0, t2);
        float2 r1 = cmul(w1, cadd(t1, t3));
        float2 r2 = cmul(w2, csub(t0, t2));
        float2 r3 = cmul(w3, csub(t1, t3));
        if (SEL) {
            y[mapA(o)]         = r0;
            y[mapA(o + M)]     = r1;
            y[mapA(o + 2 * M)] = r2;
            y[mapA(o + 3 * M)] = r3;
        } else {
            y[mapB(o)]         = r0;
            y[mapB(o + M)]     = r1;
            y[mapB(o + 2 * M)] = r2;
            y[mapB(o + 3 * M)] = r3;
        }
    }
    __syncthreads();
}

__device__ __forceinline__ void fft1024_r4(float2* A, float2* B,
                                           const float2* tw1, const float2* tw2, int t)
{
    r4stage<1,   0>(A, B, tw1, tw2, t);
    r4stage<4,   1>(B, A, tw1, tw2, t);
    r4stage<16,  0>(A, B, tw1, tw2, t);
    r4stage<64,  1>(B, A, tw1, tw2, t);
    r4stage<256, 0>(A, B, tw1, tw2, t);
}

// ------- forward: two real rows per block, Hermitian-half fp16 output ---------
__global__ __launch_bounds__(128) void fft_fwd()
{
    __shared__ float2 bufA[1280];
    __shared__ float2 bufB[1024];
    __shared__ float2 tw1[256];
    __shared__ float2 tw2[256];
    const int which = blockIdx.y;
    const int rp = blockIdx.x;
    const __half2* __restrict__ A2 = (const __half2*)&g_qkv[which][2 * rp][0];
    const __half2* __restrict__ B2 = (const __half2*)&g_qkv[which][2 * rp + 1][0];
    const int t = threadIdx.x;
    build_tw(tw1, tw2, t);
#pragma unroll
    for (int i = 0; i < 4; i++) {
        int p = t + i * 128;
        float2 fa = __half22float2(A2[p]);
        float2 fb = __half22float2(B2[p]);
        bufA[mapA(2 * p)]     = make_float2(fa.x, fb.x);
        bufA[mapA(2 * p + 1)] = make_float2(fa.y, fb.y);
    }
    __syncthreads();
    fft1024_r4(bufA, bufB, tw1, tw2, t);

    __half2* __restrict__ base16 = (which == 0) ? g_fq : (which == 1) ? g_fk : g_fv;
    __half2* __restrict__ dA = base16 + (size_t)(2 * rp) * DH;
    __half2* __restrict__ dB = base16 + (size_t)(2 * rp + 1) * DH;

#pragma unroll
    for (int q = 0; q < 4; q++) {
        int k = t + q * 128;
        float2 oA, oB;
        if (k == 0) {
            float2 z0 = bufB[mapB(0)], zn = bufB[mapB(512)];
            oA = make_float2(z0.x, zn.x);
            oB = make_float2(z0.y, zn.y);
        } else {
            float2 u = bufB[mapB(k)];
            float2 v = bufB[mapB(1024 - k)];
            float2 cv = make_float2(v.x, -v.y);
            float2 s = cadd(u, cv);
            float2 d = csub(u, cv);
            oA = make_float2(0.5f * s.x, 0.5f * s.y);
            oB = make_float2(0.5f * d.y, -0.5f * d.x);
        }
        dA[k] = __floats2half2_rn(oA.x, oA.y);
        dB[k] = __floats2half2_rn(oB.x, oB.y);
    }
}

// ------- inverse: two real rows per block from fp16 Hermitian halves ----------
// FOUT already scaled by 1/1024 in the scan, so no invn here.
__global__ __launch_bounds__(128) void fft_inv(float* __restrict__ out)
{
    __shared__ float2 bufA[1280];
    __shared__ float2 bufB[1024];
    __shared__ float2 tw1[256];
    __shared__ float2 tw2[256];
    const int rp = blockIdx.x;
    const __half2* __restrict__ Ha = g_fq + (size_t)(2 * rp) * DH;
    const __half2* __restrict__ Hb = g_fq + (size_t)(2 * rp + 1) * DH;
    float* __restrict__ dA = &out[(size_t)(2 * rp) * DD];
    float* __restrict__ dB = &out[(size_t)(2 * rp + 1) * DD];
    const int t = threadIdx.x;
    build_tw(tw1, tw2, t);
#pragma unroll
    for (int q = 0; q < 4; q++) {
        int k = t + q * 128;
        float2 A = __half22float2(Ha[k]);
        float2 B = __half22float2(Hb[k]);
        if (k == 0) {
            bufA[mapA(0)]   = make_float2(A.x, -B.x);
            bufA[mapA(512)] = make_float2(A.y, -B.y);
        } else {
            bufA[mapA(k)]        = make_float2(A.x - B.y, -(A.y + B.x));
            bufA[mapA(1024 - k)] = make_float2(A.x + B.y, A.y - B.x);
        }
    }
    __syncthreads();
    fft1024_r4(bufA, bufB, tw1, tw2, t);
#pragma unroll
    for (int i = 0; i < 8; i++) {
        int idx = t + i * 128;
        float2 w = bufB[mapB(idx)];
        dA[idx] = w.x;
        dB[idx] = -w.y;
    }
}

// ---------------- causal scan of fk*fv, unbind with conj(fq) ------------------
__global__ __launch_bounds__(128) void scanA()
{
    const int chunk = blockIdx.x;
    const int dt = blockIdx.y;
    const int b = blockIdx.z;
    const int d = dt * 128 + threadIdx.x;
    size_t base = ((size_t)b * SS + (size_t)chunk * CHUNKLEN) * DH + d;
    float2 acc = make_float2(0.f, 0.f);
    if (d == 0) {
#pragma unroll 4
        for (int s = 0; s < CHUNKLEN; s++) {
            float2 fk = __half22float2(g_fk[base + (size_t)s * DH]);
            float2 fv = __half22float2(g_fv[base + (size_t)s * DH]);
            acc.x += fk.x * fv.x;
            acc.y += fk.y * fv.y;
        }
    } else {
#pragma unroll 4
        for (int s = 0; s < CHUNKLEN; s++) {
            float2 fk = __half22float2(g_fk[base + (size_t)s * DH]);
            float2 fv = __half22float2(g_fv[base + (size_t)s * DH]);
            acc.x += fk.x * fv.x - fk.y * fv.y;
            acc.y += fk.x * fv.y + fk.y * fv.x;
        }
    }
    g_chunk[b][chunk][d] = acc;
}

__global__ __launch_bounds__(128) void scanC()
{
    const int chunk = blockIdx.x;
    const int dt = blockIdx.y;
    const int b = blockIdx.z;
    const int d = dt * 128 + threadIdx.x;
    size_t base = ((size_t)b * SS + (size_t)chunk * CHUNKLEN) * DH + d;
    float2 acc = make_float2(0.f, 0.f);
    for (int c = 0; c < chunk; c++) {
        float2 p = g_chunk[b][c][d];
        acc.x += p.x; acc.y += p.y;
    }
    const float sc = 1.0f / 1024.0f;
    if (d == 0) {
#pragma unroll 4
        for (int s = 0; s < CHUNKLEN; s++) {
            float2 fk = __half22float2(g_fk[base + (size_t)s * DH]);
            float2 fv = __half22float2(g_fv[base + (size_t)s * DH]);
            acc.x += fk.x * fv.x;
            acc.y += fk.y * fv.y;
            float2 fq = __half22float2(g_fq[base + (size_t)s * DH]);
            g_fq[base + (size_t)s * DH] =
                __floats2half2_rn(acc.x * fq.x * sc, acc.y * fq.y * sc);
        }
    } else {
#pragma unroll 4
        for (int s = 0; s < CHUNKLEN; s++) {
            float2 fk = __half22float2(g_fk[base + (size_t)s * DH]);
            float2 fv = __half22float2(g_fv[base + (size_t)s * DH]);
            acc.x += fk.x * fv.x - fk.y * fv.y;
            acc.y += fk.x * fv.y + fk.y * fv.x;
            float2 fq = __half22float2(g_fq[base + (size_t)s * DH]);
            float2 o = make_float2((acc.x * fq.x + acc.y * fq.y) * sc,
                                   (acc.y * fq.x - acc.x * fq.y) * sc);
            g_fq[base + (size_t)s * DH] = __floats2half2_rn(o.x, o.y);
        }
    }
}

// ---------------- launch ------------------------------------------------------
extern "C" void kernel_launch(void* const* d_in, const int* in_sizes, int n_in,
                              void* d_out, int out_size)
{
    const float* x  = (const float*)d_in[0];
    const float* Wq = (const float*)d_in[1];
    const float* Wk = (const float*)d_in[2];
    const float* Wv = (const float*)d_in[3];
    float* out = (float*)d_out;

    conv_all<<<XBLK + 3 * WBLK, 256>>>(x, Wq, Wk, Wv);

    cudaFuncSetAttribute(gemm_hmma, cudaFuncAttributeMaxDynamicSharedMemorySize, GEMM_SMEM_BYTES);
    gemm_hmma<<<dim3(DD / NT, MM / MT, 3), 256, GEMM_SMEM_BYTES>>>();

    fft_fwd<<<dim3(MM / 2, 3), 128>>>();

    dim3 sgrid(NCHUNK, DH / 128, BB);   // (64, 4, 4) = 1024 blocks
    scanA<<<sgrid, 128>>>();
    scanC<<<sgrid, 128>>>();

    fft_inv<<<MM / 2, 128>>>(out);
}

// round 14
// speedup vs baseline: 1.0217x; 1.0217x over previous
#include <cuda_runtime.h>
#include <cuda_fp16.h>
#include <math_constants.h>
#include <cstdint>

#define BB 4
#define SS 2048
#define DD 1024
#define MM (BB*SS)          // 8192 rows
#define DH 512              // stored half-spectrum bins (Nyquist packed into bin0.y)
#define NCHUNK 128
#define CHUNKLEN (SS/NCHUNK) // 16

// GEMM tiling
#define MT 128
#define NT 128
#define KC 64
#define NKCH (DD/KC)        // 16

// convert-kernel grid split
#define XBLK ((MM * DD) / 1024)   // 8192
#define WBLK ((DD * DD) / 1024)   // 1024

// ---------------- scratch (static device memory; no allocations) -------------
__device__ __half  g_qkv[3][MM][DD];                // Q,K,V fp16  (48 MB)
__device__ __half2 g_fq[(size_t)MM * DH];           // FQ fp16; overwritten as FOUT/1024
__device__ __half2 g_fk[(size_t)MM * DH];           // FK fp16 complex (16.8 MB)
__device__ __half2 g_fv[(size_t)MM * DH];           // FV fp16 complex (16.8 MB)
__device__ float2  g_chunk[BB][NCHUNK][DH];         // per-chunk partial sums (2 MB)
__device__ __half  g_x16[(size_t)MM * DD];          // 16 MB
__device__ __half  g_w[3][DD * DD];                 // 6 MB

// ---------------- PTX helpers -------------------------------------------------
__device__ __forceinline__ uint32_t smem_u32(const void* p) {
    uint32_t a;
    asm("{ .reg .u64 t; cvta.to.shared.u64 t, %1; cvt.u32.u64 %0, t; }" : "=r"(a) : "l"(p));
    return a;
}
__device__ __forceinline__ void cp16(uint32_t dst, const void* src) {
    asm volatile("cp.async.cg.shared.global [%0], [%1], 16;" :: "r"(dst), "l"(src) : "memory");
}
__device__ __forceinline__ void cp_commit() { asm volatile("cp.async.commit_group;" ::: "memory"); }
__device__ __forceinline__ void cp_wait2()  { asm volatile("cp.async.wait_group 2;" ::: "memory"); }

__device__ __forceinline__ void ldsm4(uint32_t* r, uint32_t addr) {
    asm volatile("ldmatrix.sync.aligned.m8n8.x4.shared.b16 {%0,%1,%2,%3}, [%4];"
        : "=r"(r[0]), "=r"(r[1]), "=r"(r[2]), "=r"(r[3]) : "r"(addr));
}
__device__ __forceinline__ void hmma(float* c, const uint32_t* a, const uint32_t* b) {
    asm volatile("mma.sync.aligned.m16n8k16.row.col.f32.f16.f16.f32 "
        "{%0,%1,%2,%3}, {%4,%5,%6,%7}, {%8,%9}, {%0,%1,%2,%3};"
        : "+f"(c[0]), "+f"(c[1]), "+f"(c[2]), "+f"(c[3])
        : "r"(a[0]), "r"(a[1]), "r"(a[2]), "r"(a[3]), "r"(b[0]), "r"(b[1]));
}

// ---------------- fused fp16 convert kernel -----------------------------------
__global__ __launch_bounds__(256) void conv_all(const float* __restrict__ X,
                                                const float* __restrict__ Wq,
                                                const float* __restrict__ Wk,
                                                const float* __restrict__ Wv) {
    const int b = blockIdx.x;
    const float* __restrict__ src;
    __half* __restrict__ dst;
    int blk;
    if (b < XBLK) {
        src = X; dst = g_x16; blk = b;
    } else {
        int wb = b - XBLK;
        int which = wb / WBLK;
        src = (which == 0) ? Wq : (which == 1) ? Wk : Wv;
        dst = g_w[which];
        blk = wb - which * WBLK;
    }
    size_t i = ((size_t)blk * 256 + threadIdx.x) * 4;
    float4 v = *(const float4*)(src + i);
    __half h[4];
    h[0] = __float2half_rn(v.x);
    h[1] = __float2half_rn(v.y);
    h[2] = __float2half_rn(v.z);
    h[3] = __float2half_rn(v.w);
    *(uint2*)&dst[i] = *(uint2*)h;
}

// ---------------- HMMA GEMM: Y = X * W^T  (fp16, fp32 accum, fp16 out) --------
#define GSM_BUF   32768
#define OFF_A     0
#define OFF_B     16384
#define GEMM_SMEM_BYTES (100 * 1024)

__device__ __forceinline__ uint32_t sw128(uint32_t bo) {
    return bo ^ ((bo >> 3) & 0x70);
}

__device__ __forceinline__ void load_chunk(uint32_t sb, int buf, int ch, int m0, int n0, int tid,
                                           const __half* __restrict__ Ax,
                                           const __half* __restrict__ Bw) {
    const int c0 = ch * KC;
    const uint32_t base = sb + buf * GSM_BUF;
#pragma unroll
    for (int i = 0; i < 4; i++) {
        int seg = tid + i * 256;
        int row = seg >> 3;
        int sc  = seg & 7;
        uint32_t sw = sw128((uint32_t)(row * 128 + sc * 16));
        size_t ga = (size_t)(m0 + row) * DD + c0 + sc * 8;
        size_t gb = (size_t)(n0 + row) * DD + c0 + sc * 8;
        cp16(base + OFF_A + sw, Ax + ga);
        cp16(base + OFF_B + sw, Bw + gb);
    }
}

__global__ __launch_bounds__(256) void gemm_hmma() {
    extern __shared__ __align__(16) char smem_raw[];
    uint32_t raw = smem_u32(smem_raw);
    uint32_t sb = (raw + 1023) & ~1023u;

    const int tid = threadIdx.x;
    const int wid = tid >> 5;
    const int l   = tid & 31;
    const int which = blockIdx.z;
    const int m0 = blockIdx.y * MT;
    const int n0 = blockIdx.x * NT;
    const int warp_m = (wid & 3) * 32;
    const int warp_n = (wid >> 2) * 64;

    const __half* __restrict__ Ax = g_x16;
    const __half* __restrict__ Bw = g_w[which];
    __half* __restrict__ Y = &g_qkv[which][0][0];

    float acc[2][8][4];
#pragma unroll
    for (int i = 0; i < 2; i++)
#pragma unroll
        for (int j = 0; j < 8; j++)
#pragma unroll
            for (int k = 0; k < 4; k++) acc[i][j][k] = 0.f;

    const int a_row = (l & 15);
    const int a_k16 = (l >> 4);
    const int b_row = (l & 7) + ((l >> 4) & 1) * 8;
    const int b_k16 = (l >> 3) & 1;

    load_chunk(sb, 0, 0, m0, n0, tid, Ax, Bw);
    cp_commit();
    load_chunk(sb, 1, 1, m0, n0, tid, Ax, Bw);
    cp_commit();

    for (int c = 0; c < NKCH; c++) {
        if (c + 2 < NKCH)
            load_chunk(sb, (c + 2) % 3, c + 2, m0, n0, tid, Ax, Bw);
        cp_commit();
        cp_wait2();
        __syncthreads();

        const uint32_t base = sb + (c % 3) * GSM_BUF;
#pragma unroll
        for (int ks = 0; ks < 4; ks++) {
            uint32_t ax[2][4], bw[8][2];
#pragma unroll
            for (int mt = 0; mt < 2; mt++) {
                uint32_t bo = (uint32_t)((warp_m + mt * 16 + a_row) * 128 + (ks * 2 + a_k16) * 16);
                uint32_t sw = sw128(bo);
                ldsm4(ax[mt], base + OFF_A + sw);
            }
#pragma unroll
            for (int p = 0; p < 4; p++) {
                uint32_t bo = (uint32_t)((warp_n + p * 16 + b_row) * 128 + (ks * 2 + b_k16) * 16);
                uint32_t sw = sw128(bo);
                uint32_t r[4];
                ldsm4(r, base + OFF_B + sw);
                bw[2 * p][0] = r[0]; bw[2 * p][1] = r[1];
                bw[2 * p + 1][0] = r[2]; bw[2 * p + 1][1] = r[3];
            }
#pragma unroll
            for (int mt = 0; mt < 2; mt++)
#pragma unroll
                for (int nt = 0; nt < 8; nt++)
                    hmma(acc[mt][nt], ax[mt], bw[nt]);
        }
        __syncthreads();
    }

    const int g = l >> 2;
    const int t = l & 3;
#pragma unroll
    for (int mt = 0; mt < 2; mt++)
#pragma unroll
        for (int nt = 0; nt < 8; nt++) {
            int m = m0 + warp_m + mt * 16 + g;
            int n = n0 + warp_n + nt * 8 + t * 2;
            __half2 h01 = __floats2half2_rn(acc[mt][nt][0], acc[mt][nt][1]);
            __half2 h23 = __floats2half2_rn(acc[mt][nt][2], acc[mt][nt][3]);
            *(__half2*)&Y[(size_t)m * DD + n]       = h01;
            *(__half2*)&Y[(size_t)(m + 8) * DD + n] = h23;
        }
}

// ---------------- 1024-point complex FFT (radix-4 Stockham, bank-aware) -------
__device__ __forceinline__ float2 cadd(float2 a, float2 b) { return make_float2(a.x + b.x, a.y + b.y); }
__device__ __forceinline__ float2 csub(float2 a, float2 b) { return make_float2(a.x - b.x, a.y - b.y); }
__device__ __forceinline__ float2 cmul(float2 a, float2 b) {
    return make_float2(a.x * b.x - a.y * b.y, a.x * b.y + a.y * b.x);
}

__device__ __forceinline__ int mapA(int i) { return i + ((i >> 4) << 2); }
__device__ __forceinline__ int mapB(int i) { return i ^ ((i >> 4) & 3); }

template<int M, int SEL>
__device__ __forceinline__ void r4stage(const float2* __restrict__ x, float2* __restrict__ y, int t)
{
#pragma unroll
    for (int q = 0; q < 2; q++) {
        int bf = t + q * 128;
        int j = bf / M;
        int k = bf - j * M;
        float2 c0 = x[SEL ? mapB(bf)       : mapA(bf)];
        float2 c1 = x[SEL ? mapB(bf + 256) : mapA(bf + 256)];
        float2 c2 = x[SEL ? mapB(bf + 512) : mapA(bf + 512)];
        float2 c3 = x[SEL ? mapB(bf + 768) : mapA(bf + 768)];
        float2 t0 = cadd(c0, c2);
        float2 t1 = csub(c0, c2);
        float2 t2 = cadd(c1, c3);
        float2 d  = csub(c1, c3);
        float2 t3 = make_float2(d.y, -d.x);   // -i * d
        float ang = -(2.0f * (float)CUDART_PI_F / 1024.0f) * (float)(j * M);
        float sn, cs;
        __sincosf(ang, &sn, &cs);
        float2 w1 = make_float2(cs, sn);
        float2 w2 = cmul(w1, w1);
        float2 w3 = cmul(w1, w2);
        int o = k + 4 * j * M;
        float2 r0 = cadd(t0, t2);
        float2 r1 = cmul(w1, cadd(t1, t3));
        float2 r2 = cmul(w2, csub(t0, t2));
        float2 r3 = cmul(w3, csub(t1, t3));
        if (SEL) {
            y[mapA(o)]         = r0;
            y[mapA(o + M)]     = r1;
            y[mapA(o + 2 * M)] = r2;
            y[mapA(o + 3 * M)] = r3;
        } else {
            y[mapB(o)]         = r0;
            y[mapB(o + M)]     = r1;
            y[mapB(o + 2 * M)] = r2;
            y[mapB(o + 3 * M)] = r3;
        }
    }
    __syncthreads();
}

__device__ __forceinline__ void fft1024_r4(float2* A, float2* B, int t)
{
    r4stage<1,   0>(A, B, t);
    r4stage<4,   1>(B, A, t);
    r4stage<16,  0>(A, B, t);
    r4stage<64,  1>(B, A, t);
    r4stage<256, 0>(A, B, t);
}

// ------- forward: two real rows per block, Hermitian-half fp16 output ---------
__global__ __launch_bounds__(128) void fft_fwd()
{
    __shared__ float2 bufA[1280];
    __shared__ float2 bufB[1024];
    const int which = blockIdx.y;
    const int rp = blockIdx.x;
    const __half2* __restrict__ A2 = (const __half2*)&g_qkv[which][2 * rp][0];
    const __half2* __restrict__ B2 = (const __half2*)&g_qkv[which][2 * rp + 1][0];
    const int t = threadIdx.x;
#pragma unroll
    for (int i = 0; i < 4; i++) {
        int p = t + i * 128;
        float2 fa = __half22float2(A2[p]);
        float2 fb = __half22float2(B2[p]);
        bufA[mapA(2 * p)]     = make_float2(fa.x, fb.x);
        bufA[mapA(2 * p + 1)] = make_float2(fa.y, fb.y);
    }
    __syncthreads();
    fft1024_r4(bufA, bufB, t);

    __half2* __restrict__ base16 = (which == 0) ? g_fq : (which == 1) ? g_fk : g_fv;
    __half2* __restrict__ dA = base16 + (size_t)(2 * rp) * DH;
    __half2* __restrict__ dB = base16 + (size_t)(2 * rp + 1) * DH;

#pragma unroll
    for (int q = 0; q < 4; q++) {
        int k = t + q * 128;
        float2 oA, oB;
        if (k == 0) {
            float2 z0 = bufB[mapB(0)], zn = bufB[mapB(512)];
            oA = make_float2(z0.x, zn.x);
            oB = make_float2(z0.y, zn.y);
        } else {
            float2 u = bufB[mapB(k)];
            float2 v = bufB[mapB(1024 - k)];
            float2 cv = make_float2(v.x, -v.y);
            float2 s = cadd(u, cv);
            float2 d = csub(u, cv);
            oA = make_float2(0.5f * s.x, 0.5f * s.y);
            oB = make_float2(0.5f * d.y, -0.5f * d.x);
        }
        dA[k] = __floats2half2_rn(oA.x, oA.y);
        dB[k] = __floats2half2_rn(oB.x, oB.y);
    }
}

// ------- inverse: two real rows per block from fp16 Hermitian halves ----------
// FOUT already scaled by 1/1024 in the scan, so no invn here.
__global__ __launch_bounds__(128) void fft_inv(float* __restrict__ out)
{
    __shared__ float2 bufA[1280];
    __shared__ float2 bufB[1024];
    const int rp = blockIdx.x;
    const __half2* __restrict__ Ha = g_fq + (size_t)(2 * rp) * DH;
    const __half2* __restrict__ Hb = g_fq + (size_t)(2 * rp + 1) * DH;
    float* __restrict__ dA = &out[(size_t)(2 * rp) * DD];
    float* __restrict__ dB = &out[(size_t)(2 * rp + 1) * DD];
    const int t = threadIdx.x;
#pragma unroll
    for (int q = 0; q < 4; q++) {
        int k = t + q * 128;
        float2 A = __half22float2(Ha[k]);
        float2 B = __half22float2(Hb[k]);
        if (k == 0) {
            bufA[mapA(0)]   = make_float2(A.x, -B.x);
            bufA[mapA(512)] = make_float2(A.y, -B.y);
        } else {
            bufA[mapA(k)]        = make_float2(A.x - B.y, -(A.y + B.x));
            bufA[mapA(1024 - k)] = make_float2(A.x + B.y, A.y - B.x);
        }
    }
    __syncthreads();
    fft1024_r4(bufA, bufB, t);
#pragma unroll
    for (int i = 0; i < 8; i++) {
        int idx = t + i * 128;
        float2 w = bufB[mapB(idx)];
        dA[idx] = w.x;
        dB[idx] = -w.y;
    }
}

// ---------------- causal scan of fk*fv, unbind with conj(fq) ------------------
__global__ __launch_bounds__(128) void scanA()
{
    const int chunk = blockIdx.x;
    const int dt = blockIdx.y;
    const int b = blockIdx.z;
    const int d = dt * 128 + threadIdx.x;
    size_t base = ((size_t)b * SS + (size_t)chunk * CHUNKLEN) * DH + d;
    float2 acc = make_float2(0.f, 0.f);
    if (d == 0) {
#pragma unroll 4
        for (int s = 0; s < CHUNKLEN; s++) {
            float2 fk = __half22float2(g_fk[base + (size_t)s * DH]);
            float2 fv = __half22float2(g_fv[base + (size_t)s * DH]);
            acc.x += fk.x * fv.x;
            acc.y += fk.y * fv.y;
        }
    } else {
#pragma unroll 4
        for (int s = 0; s < CHUNKLEN; s++) {
            float2 fk = __half22float2(g_fk[base + (size_t)s * DH]);
            float2 fv = __half22float2(g_fv[base + (size_t)s * DH]);
            acc.x += fk.x * fv.x - fk.y * fv.y;
            acc.y += fk.x * fv.y + fk.y * fv.x;
        }
    }
    g_chunk[b][chunk][d] = acc;
}

__global__ __launch_bounds__(128) void scanC()
{
    const int chunk = blockIdx.x;
    const int dt = blockIdx.y;
    const int b = blockIdx.z;
    const int d = dt * 128 + threadIdx.x;
    size_t base = ((size_t)b * SS + (size_t)chunk * CHUNKLEN) * DH + d;
    float2 acc = make_float2(0.f, 0.f);
    for (int c = 0; c < chunk; c++) {
        float2 p = g_chunk[b][c][d];
        acc.x += p.x; acc.y += p.y;
    }
    const float sc = 1.0f / 1024.0f;
    if (d == 0) {
#pragma unroll 4
        for (int s = 0; s < CHUNKLEN; s++) {
            float2 fk = __half22float2(g_fk[base + (size_t)s * DH]);
            float2 fv = __half22float2(g_fv[base + (size_t)s * DH]);
            acc.x += fk.x * fv.x;
            acc.y += fk.y * fv.y;
            float2 fq = __half22float2(g_fq[base + (size_t)s * DH]);
            g_fq[base + (size_t)s * DH] =
                __floats2half2_rn(acc.x * fq.x * sc, acc.y * fq.y * sc);
        }
    } else {
#pragma unroll 4
        for (int s = 0; s < CHUNKLEN; s++) {
            float2 fk = __half22float2(g_fk[base + (size_t)s * DH]);
            float2 fv = __half22float2(g_fv[base + (size_t)s * DH]);
            acc.x += fk.x * fv.x - fk.y * fv.y;
            acc.y += fk.x * fv.y + fk.y * fv.x;
            float2 fq = __half22float2(g_fq[base + (size_t)s * DH]);
            float2 o = make_float2((acc.x * fq.x + acc.y * fq.y) * sc,
                                   (acc.y * fq.x - acc.x * fq.y) * sc);
            g_fq[base + (size_t)s * DH] = __floats2half2_rn(o.x, o.y);
        }
    }
}

// ---------------- launch ------------------------------------------------------
extern "C" void kernel_launch(void* const* d_in, const int* in_sizes, int n_in,
                              void* d_out, int out_size)
{
    const float* x  = (const float*)d_in[0];
    const float* Wq = (const float*)d_in[1];
    const float* Wk = (const float*)d_in[2];
    const float* Wv = (const float*)d_in[3];
    float* out = (float*)d_out;

    conv_all<<<XBLK + 3 * WBLK, 256>>>(x, Wq, Wk, Wv);

    cudaFuncSetAttribute(gemm_hmma, cudaFuncAttributeMaxDynamicSharedMemorySize, GEMM_SMEM_BYTES);
    gemm_hmma<<<dim3(DD / NT, MM / MT, 3), 256, GEMM_SMEM_BYTES>>>();

    fft_fwd<<<dim3(MM / 2, 3), 128>>>();

    dim3 sgrid(NCHUNK, DH / 128, BB);   // (128, 4, 4) = 2048 blocks
    scanA<<<sgrid, 128>>>();
    scanC<<<sgrid, 128>>>();

    fft_inv<<<MM / 2, 128>>>(out);
}

// round 15
// speedup vs baseline: 1.0606x; 1.0380x over previous
#include <cuda_runtime.h>
#include <cuda_fp16.h>
#include <math_constants.h>
#include <cstdint>

#define BB 4
#define SS 2048
#define DD 1024
#define MM (BB*SS)          // 8192 rows
#define DH 512              // stored half-spectrum bins (Nyquist packed into bin0.y)
#define NCHUNK 128
#define CHUNKLEN (SS/NCHUNK) // 16

// GEMM tiling
#define MT 128
#define NT 128
#define KC 64
#define NKCH (DD/KC)        // 16

// convert-kernel grid split
#define XBLK ((MM * DD) / 1024)   // 8192
#define WBLK ((DD * DD) / 1024)   // 1024

// ---------------- scratch (static device memory; no allocations) -------------
__device__ __half  g_qkv[3][MM][DD];                // Q,K,V fp16  (48 MB)
__device__ __half2 g_fq[(size_t)MM * DH];           // FQ fp16; overwritten as FOUT/1024
__device__ __half2 g_fk[(size_t)MM * DH];           // FK fp16 complex (16.8 MB)
__device__ __half2 g_fv[(size_t)MM * DH];           // FV fp16 complex (16.8 MB)
__device__ float2  g_chunk[BB][NCHUNK][DH];         // per-chunk partial sums (2 MB)
__device__ __half  g_x16[(size_t)MM * DD];          // 16 MB
__device__ __half  g_w[3][DD * DD];                 // 6 MB

// ---------------- PTX helpers -------------------------------------------------
__device__ __forceinline__ uint32_t smem_u32(const void* p) {
    uint32_t a;
    asm("{ .reg .u64 t; cvta.to.shared.u64 t, %1; cvt.u32.u64 %0, t; }" : "=r"(a) : "l"(p));
    return a;
}
__device__ __forceinline__ void cp16(uint32_t dst, const void* src) {
    asm volatile("cp.async.cg.shared.global [%0], [%1], 16;" :: "r"(dst), "l"(src) : "memory");
}
__device__ __forceinline__ void cp_commit() { asm volatile("cp.async.commit_group;" ::: "memory"); }
__device__ __forceinline__ void cp_wait1()  { asm volatile("cp.async.wait_group 1;" ::: "memory"); }
__device__ __forceinline__ void cp_wait0()  { asm volatile("cp.async.wait_group 0;" ::: "memory"); }

__device__ __forceinline__ void ldsm4(uint32_t* r, uint32_t addr) {
    asm volatile("ldmatrix.sync.aligned.m8n8.x4.shared.b16 {%0,%1,%2,%3}, [%4];"
        : "=r"(r[0]), "=r"(r[1]), "=r"(r[2]), "=r"(r[3]) : "r"(addr));
}
__device__ __forceinline__ void hmma(float* c, const uint32_t* a, const uint32_t* b) {
    asm volatile("mma.sync.aligned.m16n8k16.row.col.f32.f16.f16.f32 "
        "{%0,%1,%2,%3}, {%4,%5,%6,%7}, {%8,%9}, {%0,%1,%2,%3};"
        : "+f"(c[0]), "+f"(c[1]), "+f"(c[2]), "+f"(c[3])
        : "r"(a[0]), "r"(a[1]), "r"(a[2]), "r"(a[3]), "r"(b[0]), "r"(b[1]));
}

// ---------------- fused fp16 convert kernel -----------------------------------
__global__ __launch_bounds__(256) void conv_all(const float* __restrict__ X,
                                                const float* __restrict__ Wq,
                                                const float* __restrict__ Wk,
                                                const float* __restrict__ Wv) {
    const int b = blockIdx.x;
    const float* __restrict__ src;
    __half* __restrict__ dst;
    int blk;
    if (b < XBLK) {
        src = X; dst = g_x16; blk = b;
    } else {
        int wb = b - XBLK;
        int which = wb / WBLK;
        src = (which == 0) ? Wq : (which == 1) ? Wk : Wv;
        dst = g_w[which];
        blk = wb - which * WBLK;
    }
    size_t i = ((size_t)blk * 256 + threadIdx.x) * 4;
    float4 v = *(const float4*)(src + i);
    __half h[4];
    h[0] = __float2half_rn(v.x);
    h[1] = __float2half_rn(v.y);
    h[2] = __float2half_rn(v.z);
    h[3] = __float2half_rn(v.w);
    *(uint2*)&dst[i] = *(uint2*)h;
}

// ---------------- HMMA GEMM: Y = X * W^T  (fp16, fp32 accum, fp16 out) --------
// 3-stage cp.async ring, ONE __syncthreads per K-chunk
#define GSM_BUF   32768
#define OFF_A     0
#define OFF_B     16384
#define GEMM_SMEM_BYTES (100 * 1024)

__device__ __forceinline__ uint32_t sw128(uint32_t bo) {
    return bo ^ ((bo >> 3) & 0x70);
}

__device__ __forceinline__ void load_chunk(uint32_t sb, int buf, int ch, int m0, int n0, int tid,
                                           const __half* __restrict__ Ax,
                                           const __half* __restrict__ Bw) {
    const int c0 = ch * KC;
    const uint32_t base = sb + buf * GSM_BUF;
#pragma unroll
    for (int i = 0; i < 4; i++) {
        int seg = tid + i * 256;
        int row = seg >> 3;
        int sc  = seg & 7;
        uint32_t sw = sw128((uint32_t)(row * 128 + sc * 16));
        size_t ga = (size_t)(m0 + row) * DD + c0 + sc * 8;
        size_t gb = (size_t)(n0 + row) * DD + c0 + sc * 8;
        cp16(base + OFF_A + sw, Ax + ga);
        cp16(base + OFF_B + sw, Bw + gb);
    }
}

__global__ __launch_bounds__(256) void gemm_hmma() {
    extern __shared__ __align__(16) char smem_raw[];
    uint32_t raw = smem_u32(smem_raw);
    uint32_t sb = (raw + 1023) & ~1023u;

    const int tid = threadIdx.x;
    const int wid = tid >> 5;
    const int l   = tid & 31;
    const int which = blockIdx.z;
    const int m0 = blockIdx.y * MT;
    const int n0 = blockIdx.x * NT;
    const int warp_m = (wid & 3) * 32;
    const int warp_n = (wid >> 2) * 64;

    const __half* __restrict__ Ax = g_x16;
    const __half* __restrict__ Bw = g_w[which];
    __half* __restrict__ Y = &g_qkv[which][0][0];

    float acc[2][8][4];
#pragma unroll
    for (int i = 0; i < 2; i++)
#pragma unroll
        for (int j = 0; j < 8; j++)
#pragma unroll
            for (int k = 0; k < 4; k++) acc[i][j][k] = 0.f;

    const int a_row = (l & 15);
    const int a_k16 = (l >> 4);
    const int b_row = (l & 7) + ((l >> 4) & 1) * 8;
    const int b_k16 = (l >> 3) & 1;

    load_chunk(sb, 0, 0, m0, n0, tid, Ax, Bw);
    cp_commit();
    load_chunk(sb, 1, 1, m0, n0, tid, Ax, Bw);
    cp_commit();

    for (int c = 0; c < NKCH; c++) {
        // chunk c resident: allow only chunk c+1's group to stay pending
        if (c + 1 < NKCH) cp_wait1(); else cp_wait0();
        __syncthreads();   // data visible + buf (c+2)%3 free (read in iter c-1)
        if (c + 2 < NKCH) {
            load_chunk(sb, (c + 2) % 3, c + 2, m0, n0, tid, Ax, Bw);
            cp_commit();
        }

        const uint32_t base = sb + (c % 3) * GSM_BUF;
#pragma unroll
        for (int ks = 0; ks < 4; ks++) {
            uint32_t ax[2][4], bw[8][2];
#pragma unroll
            for (int mt = 0; mt < 2; mt++) {
                uint32_t bo = (uint32_t)((warp_m + mt * 16 + a_row) * 128 + (ks * 2 + a_k16) * 16);
                uint32_t sw = sw128(bo);
                ldsm4(ax[mt], base + OFF_A + sw);
            }
#pragma unroll
            for (int p = 0; p < 4; p++) {
                uint32_t bo = (uint32_t)((warp_n + p * 16 + b_row) * 128 + (ks * 2 + b_k16) * 16);
                uint32_t sw = sw128(bo);
                uint32_t r[4];
                ldsm4(r, base + OFF_B + sw);
                bw[2 * p][0] = r[0]; bw[2 * p][1] = r[1];
                bw[2 * p + 1][0] = r[2]; bw[2 * p + 1][1] = r[3];
            }
#pragma unroll
            for (int mt = 0; mt < 2; mt++)
#pragma unroll
                for (int nt = 0; nt < 8; nt++)
                    hmma(acc[mt][nt], ax[mt], bw[nt]);
        }
    }

    const int g = l >> 2;
    const int t = l & 3;
#pragma unroll
    for (int mt = 0; mt < 2; mt++)
#pragma unroll
        for (int nt = 0; nt < 8; nt++) {
            int m = m0 + warp_m + mt * 16 + g;
            int n = n0 + warp_n + nt * 8 + t * 2;
            __half2 h01 = __floats2half2_rn(acc[mt][nt][0], acc[mt][nt][1]);
            __half2 h23 = __floats2half2_rn(acc[mt][nt][2], acc[mt][nt][3]);
            *(__half2*)&Y[(size_t)m * DD + n]       = h01;
            *(__half2*)&Y[(size_t)(m + 8) * DD + n] = h23;
        }
}

// ---------------- 1024-point complex FFT (radix-4 Stockham, bank-aware) -------
__device__ __forceinline__ float2 cadd(float2 a, float2 b) { return make_float2(a.x + b.x, a.y + b.y); }
__device__ __forceinline__ float2 csub(float2 a, float2 b) { return make_float2(a.x - b.x, a.y - b.y); }
__device__ __forceinline__ float2 cmul(float2 a, float2 b) {
    return make_float2(a.x * b.x - a.y * b.y, a.x * b.y + a.y * b.x);
}

__device__ __forceinline__ int mapA(int i) { return i + ((i >> 4) << 2); }
__device__ __forceinline__ int mapB(int i) { return i ^ ((i >> 4) & 3); }

template<int M, int SEL>
__device__ __forceinline__ void r4stage(const float2* __restrict__ x, float2* __restrict__ y, int t)
{
#pragma unroll
    for (int q = 0; q < 2; q++) {
        int bf = t + q * 128;
        int j = bf / M;
        int k = bf - j * M;
        float2 c0 = x[SEL ? mapB(bf)       : mapA(bf)];
        float2 c1 = x[SEL ? mapB(bf + 256) : mapA(bf + 256)];
        float2 c2 = x[SEL ? mapB(bf + 512) : mapA(bf + 512)];
        float2 c3 = x[SEL ? mapB(bf + 768) : mapA(bf + 768)];
        float2 t0 = cadd(c0, c2);
        float2 t1 = csub(c0, c2);
        float2 t2 = cadd(c1, c3);
        float2 d  = csub(c1, c3);
        float2 t3 = make_float2(d.y, -d.x);   // -i * d
        float ang = -(2.0f * (float)CUDART_PI_F / 1024.0f) * (float)(j * M);
        float sn, cs;
        __sincosf(ang, &sn, &cs);
        float2 w1 = make_float2(cs, sn);
        float2 w2 = cmul(w1, w1);
        float2 w3 = cmul(w1, w2);
        int o = k + 4 * j * M;
        float2 r0 = cadd(t0, t2);
        float2 r1 = cmul(w1, cadd(t1, t3));
        float2 r2 = cmul(w2, csub(t0, t2));
        float2 r3 = cmul(w3, csub(t1, t3));
        if (SEL) {
            y[mapA(o)]         = r0;
            y[mapA(o + M)]     = r1;
            y[mapA(o + 2 * M)] = r2;
            y[mapA(o + 3 * M)] = r3;
        } else {
            y[mapB(o)]         = r0;
            y[mapB(o + M)]     = r1;
            y[mapB(o + 2 * M)] = r2;
            y[mapB(o + 3 * M)] = r3;
        }
    }
    __syncthreads();
}

__device__ __forceinline__ void fft1024_r4(float2* A, float2* B, int t)
{
    r4stage<1,   0>(A, B, t);
    r4stage<4,   1>(B, A, t);
    r4stage<16,  0>(A, B, t);
    r4stage<64,  1>(B, A, t);
    r4stage<256, 0>(A, B, t);
}

// ------- forward: two real rows per block, Hermitian-half fp16 output ---------
__global__ __launch_bounds__(128) void fft_fwd()
{
    __shared__ float2 bufA[1280];
    __shared__ float2 bufB[1024];
    const int which = blockIdx.y;
    const int rp = blockIdx.x;
    const __half2* __restrict__ A2 = (const __half2*)&g_qkv[which][2 * rp][0];
    const __half2* __restrict__ B2 = (const __half2*)&g_qkv[which][2 * rp + 1][0];
    const int t = threadIdx.x;
#pragma unroll
    for (int i = 0; i < 4; i++) {
        int p = t + i * 128;
        float2 fa = __half22float2(A2[p]);
        float2 fb = __half22float2(B2[p]);
        bufA[mapA(2 * p)]     = make_float2(fa.x, fb.x);
        bufA[mapA(2 * p + 1)] = make_float2(fa.y, fb.y);
    }
    __syncthreads();
    fft1024_r4(bufA, bufB, t);

    __half2* __restrict__ base16 = (which == 0) ? g_fq : (which == 1) ? g_fk : g_fv;
    __half2* __restrict__ dA = base16 + (size_t)(2 * rp) * DH;
    __half2* __restrict__ dB = base16 + (size_t)(2 * rp + 1) * DH;

#pragma unroll
    for (int q = 0; q < 4; q++) {
        int k = t + q * 128;
        float2 oA, oB;
        if (k == 0) {
            float2 z0 = bufB[mapB(0)], zn = bufB[mapB(512)];
            oA = make_float2(z0.x, zn.x);
            oB = make_float2(z0.y, zn.y);
        } else {
            float2 u = bufB[mapB(k)];
            float2 v = bufB[mapB(1024 - k)];
            float2 cv = make_float2(v.x, -v.y);
            float2 s = cadd(u, cv);
            float2 d = csub(u, cv);
            oA = make_float2(0.5f * s.x, 0.5f * s.y);
            oB = make_float2(0.5f * d.y, -0.5f * d.x);
        }
        dA[k] = __floats2half2_rn(oA.x, oA.y);
        dB[k] = __floats2half2_rn(oB.x, oB.y);
    }
}

// ------- inverse: two real rows per block from fp16 Hermitian halves ----------
// FOUT already scaled by 1/1024 in the scan, so no invn here.
__global__ __launch_bounds__(128) void fft_inv(float* __restrict__ out)
{
    __shared__ float2 bufA[1280];
    __shared__ float2 bufB[1024];
    const int rp = blockIdx.x;
    const __half2* __restrict__ Ha = g_fq + (size_t)(2 * rp) * DH;
    const __half2* __restrict__ Hb = g_fq + (size_t)(2 * rp + 1) * DH;
    float* __restrict__ dA = &out[(size_t)(2 * rp) * DD];
    float* __restrict__ dB = &out[(size_t)(2 * rp + 1) * DD];
    const int t = threadIdx.x;
#pragma unroll
    for (int q = 0; q < 4; q++) {
        int k = t + q * 128;
        float2 A = __half22float2(Ha[k]);
        float2 B = __half22float2(Hb[k]);
        if (k == 0) {
            bufA[mapA(0)]   = make_float2(A.x, -B.x);
            bufA[mapA(512)] = make_float2(A.y, -B.y);
        } else {
            bufA[mapA(k)]        = make_float2(A.x - B.y, -(A.y + B.x));
            bufA[mapA(1024 - k)] = make_float2(A.x + B.y, A.y - B.x);
        }
    }
    __syncthreads();
    fft1024_r4(bufA, bufB, t);
#pragma unroll
    for (int i = 0; i < 8; i++) {
        int idx = t + i * 128;
        float2 w = bufB[mapB(idx)];
        dA[idx] = w.x;
        dB[idx] = -w.y;
    }
}

// ---------------- causal scan of fk*fv, unbind with conj(fq) ------------------
__global__ __launch_bounds__(128) void scanA()
{
    const int chunk = blockIdx.x;
    const int dt = blockIdx.y;
    const int b = blockIdx.z;
    const int d = dt * 128 + threadIdx.x;
    size_t base = ((size_t)b * SS + (size_t)chunk * CHUNKLEN) * DH + d;
    float2 acc = make_float2(0.f, 0.f);
    if (d == 0) {
#pragma unroll 4
        for (int s = 0; s < CHUNKLEN; s++) {
            float2 fk = __half22float2(g_fk[base + (size_t)s * DH]);
            float2 fv = __half22float2(g_fv[base + (size_t)s * DH]);
            acc.x += fk.x * fv.x;
            acc.y += fk.y * fv.y;
        }
    } else {
#pragma unroll 4
        for (int s = 0; s < CHUNKLEN; s++) {
            float2 fk = __half22float2(g_fk[base + (size_t)s * DH]);
            float2 fv = __half22float2(g_fv[base + (size_t)s * DH]);
            acc.x += fk.x * fv.x - fk.y * fv.y;
            acc.y += fk.x * fv.y + fk.y * fv.x;
        }
    }
    g_chunk[b][chunk][d] = acc;
}

__global__ __launch_bounds__(128) void scanC()
{
    const int chunk = blockIdx.x;
    const int dt = blockIdx.y;
    const int b = blockIdx.z;
    const int d = dt * 128 + threadIdx.x;
    size_t base = ((size_t)b * SS + (size_t)chunk * CHUNKLEN) * DH + d;
    float2 acc = make_float2(0.f, 0.f);
    for (int c = 0; c < chunk; c++) {
        float2 p = g_chunk[b][c][d];
        acc.x += p.x; acc.y += p.y;
    }
    const float sc = 1.0f / 1024.0f;
    if (d == 0) {
#pragma unroll 4
        for (int s = 0; s < CHUNKLEN; s++) {
            float2 fk = __half22float2(g_fk[base + (size_t)s * DH]);
            float2 fv = __half22float2(g_fv[base + (size_t)s * DH]);
            acc.x += fk.x * fv.x;
            acc.y += fk.y * fv.y;
            float2 fq = __half22float2(g_fq[base + (size_t)s * DH]);
            g_fq[base + (size_t)s * DH] =
                __floats2half2_rn(acc.x * fq.x * sc, acc.y * fq.y * sc);
        }
    } else {
#pragma unroll 4
        for (int s = 0; s < CHUNKLEN; s++) {
            float2 fk = __half22float2(g_fk[base + (size_t)s * DH]);
            float2 fv = __half22float2(g_fv[base + (size_t)s * DH]);
            acc.x += fk.x * fv.x - fk.y * fv.y;
            acc.y += fk.x * fv.y + fk.y * fv.x;
            float2 fq = __half22float2(g_fq[base + (size_t)s * DH]);
            float2 o = make_float2((acc.x * fq.x + acc.y * fq.y) * sc,
                                   (acc.y * fq.x - acc.x * fq.y) * sc);
            g_fq[base + (size_t)s * DH] = __floats2half2_rn(o.x, o.y);
        }
    }
}

// ---------------- launch ------------------------------------------------------
extern "C" void kernel_launch(void* const* d_in, const int* in_sizes, int n_in,
                              void* d_out, int out_size)
{
    const float* x  = (const float*)d_in[0];
    const float* Wq = (const float*)d_in[1];
    const float* Wk = (const float*)d_in[2];
    const float* Wv = (const float*)d_in[3];
    float* out = (float*)d_out;

    conv_all<<<XBLK + 3 * WBLK, 256>>>(x, Wq, Wk, Wv);

    cudaFuncSetAttribute(gemm_hmma, cudaFuncAttributeMaxDynamicSharedMemorySize, GEMM_SMEM_BYTES);
    gemm_hmma<<<dim3(DD / NT, MM / MT, 3), 256, GEMM_SMEM_BYTES>>>();

    fft_fwd<<<dim3(MM / 2, 3), 128>>>();

    dim3 sgrid(NCHUNK, DH / 128, BB);   // (128, 4, 4) = 2048 blocks
    scanA<<<sgrid, 128>>>();
    scanC<<<sgrid, 128>>>();

    fft_inv<<<MM / 2, 128>>>(out);
}

// round 16
// speedup vs baseline: 1.0971x; 1.0344x over previous
#include <cuda_runtime.h>
#include <cuda_fp16.h>
#include <math_constants.h>
#include <cstdint>

#define BB 4
#define SS 2048
#define DD 1024
#define MM (BB*SS)          // 8192 rows
#define DH 512              // stored half-spectrum bins (Nyquist packed into bin0.y)
#define NCHUNK 128
#define CHUNKLEN (SS/NCHUNK) // 16

// GEMM tiling
#define MT 128
#define NT 128
#define KC 64
#define NKCH (DD/KC)        // 16

// convert-kernel grid split
#define XBLK ((MM * DD) / 1024)   // 8192
#define WBLK ((DD * DD) / 1024)   // 1024

// ---------------- scratch (static device memory; no allocations) -------------
__device__ __half  g_qkv[3][MM][DD];                // Q,K,V fp16  (48 MB)
__device__ __half2 g_fq[(size_t)MM * DH];           // FQ fp16; overwritten as FOUT/1024
__device__ __half2 g_fk[(size_t)MM * DH];           // FK fp16 complex (16.8 MB)
__device__ __half2 g_fv[(size_t)MM * DH];           // FV fp16 complex (16.8 MB)
__device__ float2  g_chunk[BB][NCHUNK][DH];         // per-chunk partial sums (2 MB)
__device__ __half  g_x16[(size_t)MM * DD];          // 16 MB
__device__ __half  g_w[3][DD * DD];                 // 6 MB

// ---------------- PTX helpers -------------------------------------------------
__device__ __forceinline__ uint32_t smem_u32(const void* p) {
    uint32_t a;
    asm("{ .reg .u64 t; cvta.to.shared.u64 t, %1; cvt.u32.u64 %0, t; }" : "=r"(a) : "l"(p));
    return a;
}
__device__ __forceinline__ void cp16(uint32_t dst, const void* src) {
    asm volatile("cp.async.cg.shared.global [%0], [%1], 16;" :: "r"(dst), "l"(src) : "memory");
}
__device__ __forceinline__ void cp_commit() { asm volatile("cp.async.commit_group;" ::: "memory"); }
__device__ __forceinline__ void cp_wait1()  { asm volatile("cp.async.wait_group 1;" ::: "memory"); }
__device__ __forceinline__ void cp_wait0()  { asm volatile("cp.async.wait_group 0;" ::: "memory"); }

__device__ __forceinline__ void ldsm4(uint32_t* r, uint32_t addr) {
    asm volatile("ldmatrix.sync.aligned.m8n8.x4.shared.b16 {%0,%1,%2,%3}, [%4];"
        : "=r"(r[0]), "=r"(r[1]), "=r"(r[2]), "=r"(r[3]) : "r"(addr));
}
__device__ __forceinline__ void hmma(float* c, const uint32_t* a, const uint32_t* b) {
    asm volatile("mma.sync.aligned.m16n8k16.row.col.f32.f16.f16.f32 "
        "{%0,%1,%2,%3}, {%4,%5,%6,%7}, {%8,%9}, {%0,%1,%2,%3};"
        : "+f"(c[0]), "+f"(c[1]), "+f"(c[2]), "+f"(c[3])
        : "r"(a[0]), "r"(a[1]), "r"(a[2]), "r"(a[3]), "r"(b[0]), "r"(b[1]));
}

// ---------------- fused fp16 convert kernel -----------------------------------
__global__ __launch_bounds__(256) void conv_all(const float* __restrict__ X,
                                                const float* __restrict__ Wq,
                                                const float* __restrict__ Wk,
                                                const float* __restrict__ Wv) {
    const int b = blockIdx.x;
    const float* __restrict__ src;
    __half* __restrict__ dst;
    int blk;
    if (b < XBLK) {
        src = X; dst = g_x16; blk = b;
    } else {
        int wb = b - XBLK;
        int which = wb / WBLK;
        src = (which == 0) ? Wq : (which == 1) ? Wk : Wv;
        dst = g_w[which];
        blk = wb - which * WBLK;
    }
    size_t i = ((size_t)blk * 256 + threadIdx.x) * 4;
    float4 v = *(const float4*)(src + i);
    __half h[4];
    h[0] = __float2half_rn(v.x);
    h[1] = __float2half_rn(v.y);
    h[2] = __float2half_rn(v.z);
    h[3] = __float2half_rn(v.w);
    *(uint2*)&dst[i] = *(uint2*)h;
}

// ---------------- HMMA GEMM: Y = X * W^T  (fp16, fp32 accum, fp16 out) --------
// 3-stage cp.async ring, ONE __syncthreads per K-chunk, loads issued post-compute
#define GSM_BUF   32768
#define OFF_A     0
#define OFF_B     16384
#define GEMM_SMEM_BYTES (100 * 1024)

__device__ __forceinline__ uint32_t sw128(uint32_t bo) {
    return bo ^ ((bo >> 3) & 0x70);
}

__device__ __forceinline__ void load_chunk(uint32_t sb, int buf, int ch, int m0, int n0, int tid,
                                           const __half* __restrict__ Ax,
                                           const __half* __restrict__ Bw) {
    const int c0 = ch * KC;
    const uint32_t base = sb + buf * GSM_BUF;
#pragma unroll
    for (int i = 0; i < 4; i++) {
        int seg = tid + i * 256;
        int row = seg >> 3;
        int sc  = seg & 7;
        uint32_t sw = sw128((uint32_t)(row * 128 + sc * 16));
        size_t ga = (size_t)(m0 + row) * DD + c0 + sc * 8;
        size_t gb = (size_t)(n0 + row) * DD + c0 + sc * 8;
        cp16(base + OFF_A + sw, Ax + ga);
        cp16(base + OFF_B + sw, Bw + gb);
    }
}

__global__ __launch_bounds__(256) void gemm_hmma() {
    extern __shared__ __align__(16) char smem_raw[];
    uint32_t raw = smem_u32(smem_raw);
    uint32_t sb = (raw + 1023) & ~1023u;

    const int tid = threadIdx.x;
    const int wid = tid >> 5;
    const int l   = tid & 31;
    const int which = blockIdx.z;
    const int m0 = blockIdx.y * MT;
    const int n0 = blockIdx.x * NT;
    const int warp_m = (wid & 3) * 32;
    const int warp_n = (wid >> 2) * 64;

    const __half* __restrict__ Ax = g_x16;
    const __half* __restrict__ Bw = g_w[which];
    __half* __restrict__ Y = &g_qkv[which][0][0];

    float acc[2][8][4];
#pragma unroll
    for (int i = 0; i < 2; i++)
#pragma unroll
        for (int j = 0; j < 8; j++)
#pragma unroll
            for (int k = 0; k < 4; k++) acc[i][j][k] = 0.f;

    const int a_row = (l & 15);
    const int a_k16 = (l >> 4);
    const int b_row = (l & 7) + ((l >> 4) & 1) * 8;
    const int b_k16 = (l >> 3) & 1;

    load_chunk(sb, 0, 0, m0, n0, tid, Ax, Bw);
    cp_commit();
    load_chunk(sb, 1, 1, m0, n0, tid, Ax, Bw);
    cp_commit();

    for (int c = 0; c < NKCH; c++) {
        // chunk c resident: allow only chunk c+1's group to stay pending
        if (c + 1 < NKCH) cp_wait1(); else cp_wait0();
        __syncthreads();   // data visible + buf (c+2)%3 free (read in iter c-1)

        const uint32_t base = sb + (c % 3) * GSM_BUF;
#pragma unroll
        for (int ks = 0; ks < 4; ks++) {
            uint32_t ax[2][4], bw[8][2];
#pragma unroll
            for (int mt = 0; mt < 2; mt++) {
                uint32_t bo = (uint32_t)((warp_m + mt * 16 + a_row) * 128 + (ks * 2 + a_k16) * 16);
                uint32_t sw = sw128(bo);
                ldsm4(ax[mt], base + OFF_A + sw);
            }
#pragma unroll
            for (int p = 0; p < 4; p++) {
                uint32_t bo = (uint32_t)((warp_n + p * 16 + b_row) * 128 + (ks * 2 + b_k16) * 16);
                uint32_t sw = sw128(bo);
                uint32_t r[4];
                ldsm4(r, base + OFF_B + sw);
                bw[2 * p][0] = r[0]; bw[2 * p][1] = r[1];
                bw[2 * p + 1][0] = r[2]; bw[2 * p + 1][1] = r[3];
            }
#pragma unroll
            for (int mt = 0; mt < 2; mt++)
#pragma unroll
                for (int nt = 0; nt < 8; nt++)
                    hmma(acc[mt][nt], ax[mt], bw[nt]);
        }

        // prefetch chunk c+2 AFTER compute; barrier at iter c already proved
        // all warps done reading buf (c+2)%3 (their iter c-1 compute)
        if (c + 2 < NKCH) {
            load_chunk(sb, (c + 2) % 3, c + 2, m0, n0, tid, Ax, Bw);
            cp_commit();
        }
    }

    const int g = l >> 2;
    const int t = l & 3;
#pragma unroll
    for (int mt = 0; mt < 2; mt++)
#pragma unroll
        for (int nt = 0; nt < 8; nt++) {
            int m = m0 + warp_m + mt * 16 + g;
            int n = n0 + warp_n + nt * 8 + t * 2;
            __half2 h01 = __floats2half2_rn(acc[mt][nt][0], acc[mt][nt][1]);
            __half2 h23 = __floats2half2_rn(acc[mt][nt][2], acc[mt][nt][3]);
            *(__half2*)&Y[(size_t)m * DD + n]       = h01;
            *(__half2*)&Y[(size_t)(m + 8) * DD + n] = h23;
        }
}

// ---------------- 1024-point complex FFT (radix-4 Stockham, bank-aware) -------
__device__ __forceinline__ float2 cadd(float2 a, float2 b) { return make_float2(a.x + b.x, a.y + b.y); }
__device__ __forceinline__ float2 csub(float2 a, float2 b) { return make_float2(a.x - b.x, a.y - b.y); }
__device__ __forceinline__ float2 cmul(float2 a, float2 b) {
    return make_float2(a.x * b.x - a.y * b.y, a.x * b.y + a.y * b.x);
}

__device__ __forceinline__ int mapA(int i) { return i + ((i >> 4) << 2); }
__device__ __forceinline__ int mapB(int i) { return i ^ ((i >> 4) & 3); }

template<int M, int SEL>
__device__ __forceinline__ void r4stage(const float2* __restrict__ x, float2* __restrict__ y, int t)
{
#pragma unroll
    for (int q = 0; q < 2; q++) {
        int bf = t + q * 128;
        int j = bf / M;
        int k = bf - j * M;
        float2 c0 = x[SEL ? mapB(bf)       : mapA(bf)];
        float2 c1 = x[SEL ? mapB(bf + 256) : mapA(bf + 256)];
        float2 c2 = x[SEL ? mapB(bf + 512) : mapA(bf + 512)];
        float2 c3 = x[SEL ? mapB(bf + 768) : mapA(bf + 768)];
        float2 t0 = cadd(c0, c2);
        float2 t1 = csub(c0, c2);
        float2 t2 = cadd(c1, c3);
        float2 d  = csub(c1, c3);
        float2 t3 = make_float2(d.y, -d.x);   // -i * d
        float ang = -(2.0f * (float)CUDART_PI_F / 1024.0f) * (float)(j * M);
        float sn, cs;
        __sincosf(ang, &sn, &cs);
        float2 w1 = make_float2(cs, sn);
        float2 w2 = cmul(w1, w1);
        float2 w3 = cmul(w1, w2);
        int o = k + 4 * j * M;
        float2 r0 = cadd(t0, t2);
        float2 r1 = cmul(w1, cadd(t1, t3));
        float2 r2 = cmul(w2, csub(t0, t2));
        float2 r3 = cmul(w3, csub(t1, t3));
        if (SEL) {
            y[mapA(o)]         = r0;
            y[mapA(o + M)]     = r1;
            y[mapA(o + 2 * M)] = r2;
            y[mapA(o + 3 * M)] = r3;
        } else {
            y[mapB(o)]         = r0;
            y[mapB(o + M)]     = r1;
            y[mapB(o + 2 * M)] = r2;
            y[mapB(o + 3 * M)] = r3;
        }
    }
    __syncthreads();
}

// final stage M=256: j = bf/256 = 0 for all butterflies -> all twiddles = 1.
// reads mapA (SEL=0 position in the chain), writes mapB. Bit-identical to the
// general stage (cmul by exact (1,0) is value-preserving).
__device__ __forceinline__ void r4last(const float2* __restrict__ x, float2* __restrict__ y, int t)
{
#pragma unroll
    for (int q = 0; q < 2; q++) {
        int bf = t + q * 128;
        float2 c0 = x[mapA(bf)];
        float2 c1 = x[mapA(bf + 256)];
        float2 c2 = x[mapA(bf + 512)];
        float2 c3 = x[mapA(bf + 768)];
        float2 t0 = cadd(c0, c2);
        float2 t1 = csub(c0, c2);
        float2 t2 = cadd(c1, c3);
        float2 d  = csub(c1, c3);
        float2 t3 = make_float2(d.y, -d.x);   // -i * d
        y[mapB(bf)]       = cadd(t0, t2);
        y[mapB(bf + 256)] = cadd(t1, t3);
        y[mapB(bf + 512)] = csub(t0, t2);
        y[mapB(bf + 768)] = csub(t1, t3);
    }
    __syncthreads();
}

__device__ __forceinline__ void fft1024_r4(float2* A, float2* B, int t)
{
    r4stage<1,  0>(A, B, t);
    r4stage<4,  1>(B, A, t);
    r4stage<16, 0>(A, B, t);
    r4stage<64, 1>(B, A, t);
    r4last(A, B, t);
}

// ------- forward: two real rows per block, Hermitian-half fp16 output ---------
__global__ __launch_bounds__(128) void fft_fwd()
{
    __shared__ float2 bufA[1280];
    __shared__ float2 bufB[1024];
    const int which = blockIdx.y;
    const int rp = blockIdx.x;
    const __half2* __restrict__ A2 = (const __half2*)&g_qkv[which][2 * rp][0];
    const __half2* __restrict__ B2 = (const __half2*)&g_qkv[which][2 * rp + 1][0];
    const int t = threadIdx.x;
#pragma unroll
    for (int i = 0; i < 4; i++) {
        int p = t + i * 128;
        float2 fa = __half22float2(A2[p]);
        float2 fb = __half22float2(B2[p]);
        bufA[mapA(2 * p)]     = make_float2(fa.x, fb.x);
        bufA[mapA(2 * p + 1)] = make_float2(fa.y, fb.y);
    }
    __syncthreads();
    fft1024_r4(bufA, bufB, t);

    __half2* __restrict__ base16 = (which == 0) ? g_fq : (which == 1) ? g_fk : g_fv;
    __half2* __restrict__ dA = base16 + (size_t)(2 * rp) * DH;
    __half2* __restrict__ dB = base16 + (size_t)(2 * rp + 1) * DH;

#pragma unroll
    for (int q = 0; q < 4; q++) {
        int k = t + q * 128;
        float2 oA, oB;
        if (k == 0) {
            float2 z0 = bufB[mapB(0)], zn = bufB[mapB(512)];
            oA = make_float2(z0.x, zn.x);
            oB = make_float2(z0.y, zn.y);
        } else {
            float2 u = bufB[mapB(k)];
            float2 v = bufB[mapB(1024 - k)];
            float2 cv = make_float2(v.x, -v.y);
            float2 s = cadd(u, cv);
            float2 d = csub(u, cv);
            oA = make_float2(0.5f * s.x, 0.5f * s.y);
            oB = make_float2(0.5f * d.y, -0.5f * d.x);
        }
        dA[k] = __floats2half2_rn(oA.x, oA.y);
        dB[k] = __floats2half2_rn(oB.x, oB.y);
    }
}

// ------- inverse: two real rows per block from fp16 Hermitian halves ----------
// FOUT already scaled by 1/1024 in the scan, so no invn here.
__global__ __launch_bounds__(128) void fft_inv(float* __restrict__ out)
{
    __shared__ float2 bufA[1280];
    __shared__ float2 bufB[1024];
    const int rp = blockIdx.x;
    const __half2* __restrict__ Ha = g_fq + (size_t)(2 * rp) * DH;
    const __half2* __restrict__ Hb = g_fq + (size_t)(2 * rp + 1) * DH;
    float* __restrict__ dA = &out[(size_t)(2 * rp) * DD];
    float* __restrict__ dB = &out[(size_t)(2 * rp + 1) * DD];
    const int t = threadIdx.x;
#pragma unroll
    for (int q = 0; q < 4; q++) {
        int k = t + q * 128;
        float2 A = __half22float2(Ha[k]);
        float2 B = __half22float2(Hb[k]);
        if (k == 0) {
            bufA[mapA(0)]   = make_float2(A.x, -B.x);
            bufA[mapA(512)] = make_float2(A.y, -B.y);
        } else {
            bufA[mapA(k)]        = make_float2(A.x - B.y, -(A.y + B.x));
            bufA[mapA(1024 - k)] = make_float2(A.x + B.y, A.y - B.x);
        }
    }
    __syncthreads();
    fft1024_r4(bufA, bufB, t);
#pragma unroll
    for (int i = 0; i < 8; i++) {
        int idx = t + i * 128;
        float2 w = bufB[mapB(idx)];
        dA[idx] = w.x;
        dB[idx] = -w.y;
    }
}

// ---------------- causal scan of fk*fv, unbind with conj(fq) ------------------
__global__ __launch_bounds__(128) void scanA()
{
    const int chunk = blockIdx.x;
    const int dt = blockIdx.y;
    const int b = blockIdx.z;
    const int d = dt * 128 + threadIdx.x;
    size_t base = ((size_t)b * SS + (size_t)chunk * CHUNKLEN) * DH + d;
    float2 acc = make_float2(0.f, 0.f);
    if (d == 0) {
#pragma unroll 4
        for (int s = 0; s < CHUNKLEN; s++) {
            float2 fk = __half22float2(g_fk[base + (size_t)s * DH]);
            float2 fv = __half22float2(g_fv[base + (size_t)s * DH]);
            acc.x += fk.x * fv.x;
            acc.y += fk.y * fv.y;
        }
    } else {
#pragma unroll 4
        for (int s = 0; s < CHUNKLEN; s++) {
            float2 fk = __half22float2(g_fk[base + (size_t)s * DH]);
            float2 fv = __half22float2(g_fv[base + (size_t)s * DH]);
            acc.x += fk.x * fv.x - fk.y * fv.y;
            acc.y += fk.x * fv.y + fk.y * fv.x;
        }
    }
    g_chunk[b][chunk][d] = acc;
}

__global__ __launch_bounds__(128) void scanC()
{
    const int chunk = blockIdx.x;
    const int dt = blockIdx.y;
    const int b = blockIdx.z;
    const int d = dt * 128 + threadIdx.x;
    size_t base = ((size_t)b * SS + (size_t)chunk * CHUNKLEN) * DH + d;
    float2 acc = make_float2(0.f, 0.f);
    for (int c = 0; c < chunk; c++) {
        float2 p = g_chunk[b][c][d];
        acc.x += p.x; acc.y += p.y;
    }
    const float sc = 1.0f / 1024.0f;
    if (d == 0) {
#pragma unroll 4
        for (int s = 0; s < CHUNKLEN; s++) {
            float2 fk = __half22float2(g_fk[base + (size_t)s * DH]);
            float2 fv = __half22float2(g_fv[base + (size_t)s * DH]);
            acc.x += fk.x * fv.x;
            acc.y += fk.y * fv.y;
            float2 fq = __half22float2(g_fq[base + (size_t)s * DH]);
            g_fq[base + (size_t)s * DH] =
                __floats2half2_rn(acc.x * fq.x * sc, acc.y * fq.y * sc);
        }
    } else {
#pragma unroll 4
        for (int s = 0; s < CHUNKLEN; s++) {
            float2 fk = __half22float2(g_fk[base + (size_t)s * DH]);
            float2 fv = __half22float2(g_fv[base + (size_t)s * DH]);
            acc.x += fk.x * fv.x - fk.y * fv.y;
            acc.y += fk.x * fv.y + fk.y * fv.x;
            float2 fq = __half22float2(g_fq[base + (size_t)s * DH]);
            float2 o = make_float2((acc.x * fq.x + acc.y * fq.y) * sc,
                                   (acc.y * fq.x - acc.x * fq.y) * sc);
            g_fq[base + (size_t)s * DH] = __floats2half2_rn(o.x, o.y);
        }
    }
}

// ---------------- launch ------------------------------------------------------
extern "C" void kernel_launch(void* const* d_in, const int* in_sizes, int n_in,
                              void* d_out, int out_size)
{
    const float* x  = (const float*)d_in[0];
    const float* Wq = (const float*)d_in[1];
    const float* Wk = (const float*)d_in[2];
    const float* Wv = (const float*)d_in[3];
    float* out = (float*)d_out;

    conv_all<<<XBLK + 3 * WBLK, 256>>>(x, Wq, Wk, Wv);

    cudaFuncSetAttribute(gemm_hmma, cudaFuncAttributeMaxDynamicSharedMemorySize, GEMM_SMEM_BYTES);
    gemm_hmma<<<dim3(DD / NT, MM / MT, 3), 256, GEMM_SMEM_BYTES>>>();

    fft_fwd<<<dim3(MM / 2, 3), 128>>>();

    dim3 sgrid(NCHUNK, DH / 128, BB);   // (128, 4, 4) = 2048 blocks
    scanA<<<sgrid, 128>>>();
    scanC<<<sgrid, 128>>>();

    fft_inv<<<MM / 2, 128>>>(out);
}